// round 14
// baseline (speedup 1.0000x reference)
#include <cuda_runtime.h>

#define BB 2048
#define TT 512
#define II 64
#define NCHUNK 64        // 64 flag-chunks of 8 timesteps
#define CONS_BLK 64      // consumer blocks (bid 0..63)
#define PROD_BLK 4096    // producer blocks: 128 b-tiles x 32 t-tiles (16 t each)

#define XS_STRIDE 257    // float4 per b-row in smem (16t*16f4 + 1 pad)
// Request 112KB dynamic smem (we only touch 64.25KB): with ~15KB static this
// exceeds half the 228KB SM -> occupancy 1 block/SM -> consumer SMs are
// EXCLUSIVE (no producer co-residency stealing issue/LSU from the chain).
#define XS_ALLOC  114688

// Scratch [t][g][b] as float4: index (t*3+g)*BB + b holds (xr_g, xz_g, xn_g, 0).
// 8 timesteps of pad beyond t=TT are NEVER written -> stay zero; dummy lanes
// point at the pad with stride 0.
__device__ float4 g_xw4[(size_t)(TT + 8) * 3 * BB];
#define PAD_OFF ((size_t)TT * 3 * BB)

// Per-8t-chunk completion counters (128 b-tiles each). Reset every launch.
__device__ int g_flags[NCHUNK];

__device__ __forceinline__ float sigm(float x) {
    return __fdividef(1.0f, 1.0f + __expf(-x));
}
__device__ __forceinline__ float tanh_fast(float x) {
    float xc = fmaxf(x, -20.0f);
    float e = __expf(-2.0f * xc);
    return __fdividef(1.0f - e, 1.0f + e);
}
__device__ __forceinline__ int acq_load(const int* p) {
    int v;
    asm volatile("ld.acquire.gpu.b32 %0, [%1];" : "=r"(v) : "l"(p) : "memory");
    return v;
}

__global__ void reset_flags() {
    if (threadIdx.x < NCHUNK) g_flags[threadIdx.x] = 0;
}

// ---------------------------------------------------------------------------
// Fused kernel. bid < CONS_BLK: recurrence consumers (4 warps, 8 elem/warp).
// bid >= CONS_BLK: phaseA producers: 16b x 16t tile, 128 threads, each thread
// computes TWO consecutive t-cells (weight LDS amortized 2x).
// ---------------------------------------------------------------------------
__global__ void __launch_bounds__(128) fused(
    const float* __restrict__ x,
    const float* __restrict__ W_ih0, const float* __restrict__ b_ih0,
    const float* __restrict__ W_hh0, const float* __restrict__ b_hh0,
    const float* __restrict__ W_ih1, const float* __restrict__ b_ih1,
    const float* __restrict__ W_hh1, const float* __restrict__ b_hh1,
    float* __restrict__ out)
{
    extern __shared__ float4 xs[];    // [16 b][XS_STRIDE] (dynamic)
    __shared__ float4 os[48 * 16];    // [(t*3+g)][b]
    __shared__ float4 ws4[144];       // W_ih0 as [9][16] float4
    __shared__ float  bs[9];

    const int tx = threadIdx.x;

    if (blockIdx.x >= CONS_BLK) {
        // =============== PRODUCER ===============
        const int pid = blockIdx.x - CONS_BLK;
        const int b0  = (pid & 127) << 4;    // b-tile (fastest -> chunk 0 first)
        const int cnk = pid >> 7;            // 16-t tile index 0..31
        const int t0  = cnk << 4;

        if (tx < 128) ws4[tx] = ((const float4*)W_ih0)[tx];
        if (tx < 16)  ws4[128 + tx] = ((const float4*)W_ih0)[128 + tx];
        if (tx < 9)   bs[tx] = b_ih0[tx];

        // Stage 16 b-rows x 16 t x 16 f4 (4 KB contiguous per b-row).
        const float4* xg = (const float4*)x;
#pragma unroll
        for (int c = 0; c < 32; c++) {
            int f   = (c << 7) + tx;         // 0..4095
            int bl  = f >> 8;                // 256 f4 per b-row
            int off = f & 255;
            xs[bl * XS_STRIDE + off] = xg[((size_t)(b0 + bl) * TT + t0) * 16 + off];
        }
        __syncthreads();

        const int b_loc = tx & 15;
        const int tp    = tx >> 4;           // 0..7 -> t-cells 2tp, 2tp+1
        const int tl0   = tp * 2;

        float acc0[9], acc1[9];
#pragma unroll
        for (int g = 0; g < 9; g++) { acc0[g] = bs[g]; acc1[g] = bs[g]; }

#pragma unroll
        for (int i = 0; i < 16; i++) {
            float4 xv0 = xs[b_loc * XS_STRIDE + tl0 * 16 + i];
            float4 xv1 = xs[b_loc * XS_STRIDE + (tl0 + 1) * 16 + i];
#pragma unroll
            for (int g = 0; g < 9; g++) {
                float4 wv = ws4[g * 16 + i];
                acc0[g] = fmaf(xv0.w, wv.w, fmaf(xv0.z, wv.z,
                          fmaf(xv0.y, wv.y, fmaf(xv0.x, wv.x, acc0[g]))));
                acc1[g] = fmaf(xv1.w, wv.w, fmaf(xv1.z, wv.z,
                          fmaf(xv1.y, wv.y, fmaf(xv1.x, wv.x, acc1[g]))));
            }
        }

#pragma unroll
        for (int g = 0; g < 3; g++) {
            os[(tl0 * 3 + g) * 16 + b_loc] =
                make_float4(acc0[g], acc0[3 + g], acc0[6 + g], 0.f);
            os[((tl0 + 1) * 3 + g) * 16 + b_loc] =
                make_float4(acc1[g], acc1[3 + g], acc1[6 + g], 0.f);
        }
        __syncthreads();

        // 768 float4 out, 128 threads x 6 rounds, lanes consecutive in b.
#pragma unroll
        for (int r = 0; r < 6; r++) {
            int f    = r * 128 + tx;
            int pair = f >> 4;               // tt*3 + g  (0..47)
            int bl   = f & 15;
            int tt   = pair / 3, gg = pair % 3;
            g_xw4[((size_t)(t0 + tt) * 3 + gg) * BB + b0 + bl] = os[pair * 16 + bl];
        }

        __threadfence();
        __syncthreads();
        if (tx == 0) {                       // tile spans 8t-chunks 2cnk, 2cnk+1
            atomicAdd(&g_flags[2 * cnk], 1);
            atomicAdd(&g_flags[2 * cnk + 1], 1);
        }
        return;
    }

    // =============== CONSUMER (unchanged math) ===============
    const int lane = tx & 31;
    const int gw   = blockIdx.x * 4 + (tx >> 5);   // global warp 0..255
    const int j    = lane & 3;
    const int base = lane & ~3;
    const bool dum = (j == 3);
    const int g    = dum ? 0 : j;
    const int e    = gw * 8 + (lane >> 2);

    float wh0[3][3], wi1[3][3], wh1[3][3], bh0[3], bi1[3], bh1[3];
#pragma unroll
    for (int q = 0; q < 3; q++) {
        int row = q * 3 + g;
        bh0[q] = __ldg(b_hh0 + row);
        bi1[q] = __ldg(b_ih1 + row);
        bh1[q] = __ldg(b_hh1 + row);
#pragma unroll
        for (int k = 0; k < 3; k++) {
            wh0[q][k] = __ldg(W_hh0 + row * 3 + k);
            wi1[q][k] = __ldg(W_ih1 + row * 3 + k);
            wh1[q][k] = __ldg(W_hh1 + row * 3 + k);
        }
    }

    float hA = 0.f;   // h0[g]
    float hB = 0.f;   // h1[g]

    const size_t  xstr = dum ? 0 : (size_t)(3 * BB);
    const float4* xb   = g_xw4 + (dum ? PAD_OFF : ((size_t)g * BB + e));

    while (acq_load(&g_flags[0]) < 128) __nanosleep(64);

    float4 buf[8];
#pragma unroll
    for (int s = 0; s < 8; s++) buf[s] = xb[(size_t)s * xstr];

    const unsigned FULL = 0xffffffffu;

    int fv = acq_load(&g_flags[1]);

    for (int t8 = 0; t8 < 64; t8++) {
        if (t8 < 63) {
            if (fv < 128) {
                while (acq_load(&g_flags[t8 + 1]) < 128) __nanosleep(64);
            }
            int nxt = (t8 + 2 < 64) ? t8 + 2 : 63;
            fv = acq_load(&g_flags[nxt]);
        }

#pragma unroll
        for (int i = 0; i < 8; i++) {
            const int t = t8 * 8 + i;
            float4 b4 = buf[i];
            buf[i] = xb[(size_t)(t + 8) * xstr];

            float a0 = __shfl_sync(FULL, hA, base + 0);
            float a1 = __shfl_sync(FULL, hA, base + 1);
            float a2 = __shfl_sync(FULL, hA, base + 2);
            float c0 = __shfl_sync(FULL, hB, base + 0);
            float c1 = __shfl_sync(FULL, hB, base + 1);
            float c2 = __shfl_sync(FULL, hB, base + 2);

            float g0r = fmaf(wh0[0][2], a2, fmaf(wh0[0][1], a1, fmaf(wh0[0][0], a0, bh0[0])));
            float g0z = fmaf(wh0[1][2], a2, fmaf(wh0[1][1], a1, fmaf(wh0[1][0], a0, bh0[1])));
            float g0n = fmaf(wh0[2][2], a2, fmaf(wh0[2][1], a1, fmaf(wh0[2][0], a0, bh0[2])));
            float r0  = sigm(b4.x + g0r);
            float z0  = sigm(b4.y + g0z);
            float n0  = tanh_fast(fmaf(r0, g0n, b4.z));
            float hAn = fmaf(z0, hA - n0, n0);

            float i1r = fmaf(wi1[0][2], a2, fmaf(wi1[0][1], a1, fmaf(wi1[0][0], a0, bi1[0])));
            float i1z = fmaf(wi1[1][2], a2, fmaf(wi1[1][1], a1, fmaf(wi1[1][0], a0, bi1[1])));
            float i1n = fmaf(wi1[2][2], a2, fmaf(wi1[2][1], a1, fmaf(wi1[2][0], a0, bi1[2])));
            float g1r = fmaf(wh1[0][2], c2, fmaf(wh1[0][1], c1, fmaf(wh1[0][0], c0, bh1[0])));
            float g1z = fmaf(wh1[1][2], c2, fmaf(wh1[1][1], c1, fmaf(wh1[1][0], c0, bh1[1])));
            float g1n = fmaf(wh1[2][2], c2, fmaf(wh1[2][1], c1, fmaf(wh1[2][0], c0, bh1[2])));
            float r1  = sigm(i1r + g1r);
            float z1  = sigm(i1z + g1z);
            float n1  = tanh_fast(fmaf(r1, g1n, i1n));
            float hBn = fmaf(z1, hB - n1, n1);

            hA = hAn;
            hB = (t == 0) ? 0.f : hBn;
        }
    }

    // Epilogue: layer-1 consumes h0^{T-1}.
    {
        float a0 = __shfl_sync(FULL, hA, base + 0);
        float a1 = __shfl_sync(FULL, hA, base + 1);
        float a2 = __shfl_sync(FULL, hA, base + 2);
        float c0 = __shfl_sync(FULL, hB, base + 0);
        float c1 = __shfl_sync(FULL, hB, base + 1);
        float c2 = __shfl_sync(FULL, hB, base + 2);

        float i1r = fmaf(wi1[0][2], a2, fmaf(wi1[0][1], a1, fmaf(wi1[0][0], a0, bi1[0])));
        float i1z = fmaf(wi1[1][2], a2, fmaf(wi1[1][1], a1, fmaf(wi1[1][0], a0, bi1[1])));
        float i1n = fmaf(wi1[2][2], a2, fmaf(wi1[2][1], a1, fmaf(wi1[2][0], a0, bi1[2])));
        float g1r = fmaf(wh1[0][2], c2, fmaf(wh1[0][1], c1, fmaf(wh1[0][0], c0, bh1[0])));
        float g1z = fmaf(wh1[1][2], c2, fmaf(wh1[1][1], c1, fmaf(wh1[1][0], c0, bh1[1])));
        float g1n = fmaf(wh1[2][2], c2, fmaf(wh1[2][1], c1, fmaf(wh1[2][0], c0, bh1[2])));
        float r1  = sigm(i1r + g1r);
        float z1  = sigm(i1z + g1z);
        float n1  = tanh_fast(fmaf(r1, g1n, i1n));
        hB = fmaf(z1, hB - n1, n1);
    }

    if (j < 3)
        out[e * 3 + j] = hB;
}

extern "C" void kernel_launch(void* const* d_in, const int* in_sizes, int n_in,
                              void* d_out, int out_size)
{
    const float* x     = (const float*)d_in[0];
    const float* W_ih0 = (const float*)d_in[1];
    const float* W_hh0 = (const float*)d_in[2];
    const float* b_ih0 = (const float*)d_in[3];
    const float* b_hh0 = (const float*)d_in[4];
    const float* W_ih1 = (const float*)d_in[5];
    const float* W_hh1 = (const float*)d_in[6];
    const float* b_ih1 = (const float*)d_in[7];
    const float* b_hh1 = (const float*)d_in[8];
    float* out = (float*)d_out;

    cudaFuncSetAttribute(fused, cudaFuncAttributeMaxDynamicSharedMemorySize, XS_ALLOC);

    reset_flags<<<1, 64>>>();
    fused<<<CONS_BLK + PROD_BLK, 128, XS_ALLOC>>>(
        x, W_ih0, b_ih0, W_hh0, b_hh0, W_ih1, b_ih1, W_hh1, b_hh1, out);
}

// round 15
// speedup vs baseline: 1.9961x; 1.9961x over previous
#include <cuda_runtime.h>

#define BB 2048
#define TT 512
#define II 64
#define NCHUNK 64        // 64 flag-chunks of 8 timesteps
#define CONS_BLK 64      // consumer blocks (bid 0..63)
#define PROD_BLK 4096    // producer blocks: 128 b-tiles x 32 t-tiles (16 t each)

#define XS_STRIDE 257    // float4 per b-row in smem (16t*16f4 + 1 pad)
#define XS_BYTES  (16 * XS_STRIDE * 16)   // 65,792 bytes -> 2 blocks/SM (r13 config)

// Scratch [t][g][b] as float4: index (t*3+g)*BB + b holds (xr_g, xz_g, xn_g, 0).
// 8 timesteps of pad beyond t=TT are NEVER written -> stay zero; dummy lanes
// point at the pad with stride 0.
__device__ float4 g_xw4[(size_t)(TT + 8) * 3 * BB];
#define PAD_OFF ((size_t)TT * 3 * BB)

// Per-8t-chunk completion counters (128 b-tiles each). Reset every launch.
__device__ int g_flags[NCHUNK];

// Single-MUFU activations (tanh.approx.f32: ~1.3e-5 abs err; GRU update is
// contractive so accumulated output error stays ~1e-4 << 1e-3 gate).
__device__ __forceinline__ float tanh_mufu(float x) {
    float y;
    asm("tanh.approx.f32 %0, %1;" : "=f"(y) : "f"(x));
    return y;
}
__device__ __forceinline__ float sigm(float x) {
    return fmaf(0.5f, tanh_mufu(0.5f * x), 0.5f);
}
__device__ __forceinline__ float tanh_fast(float x) {
    return tanh_mufu(x);
}
__device__ __forceinline__ int acq_load(const int* p) {
    int v;
    asm volatile("ld.acquire.gpu.b32 %0, [%1];" : "=r"(v) : "l"(p) : "memory");
    return v;
}

__global__ void reset_flags() {
    if (threadIdx.x < NCHUNK) g_flags[threadIdx.x] = 0;
}

// ---------------------------------------------------------------------------
// Fused kernel (r13 structure). bid < CONS_BLK: recurrence consumers
// (4 warps, 8 elem/warp). bid >= CONS_BLK: phaseA producers: 16b x 16t tile,
// 128 threads, each thread computes TWO consecutive t-cells.
// ---------------------------------------------------------------------------
__global__ void __launch_bounds__(128) fused(
    const float* __restrict__ x,
    const float* __restrict__ W_ih0, const float* __restrict__ b_ih0,
    const float* __restrict__ W_hh0, const float* __restrict__ b_hh0,
    const float* __restrict__ W_ih1, const float* __restrict__ b_ih1,
    const float* __restrict__ W_hh1, const float* __restrict__ b_hh1,
    float* __restrict__ out)
{
    extern __shared__ float4 xs[];    // [16 b][XS_STRIDE] (dynamic, 64.25 KB)
    __shared__ float4 os[48 * 16];    // [(t*3+g)][b]
    __shared__ float4 ws4[144];       // W_ih0 as [9][16] float4
    __shared__ float  bs[9];

    const int tx = threadIdx.x;

    if (blockIdx.x >= CONS_BLK) {
        // =============== PRODUCER ===============
        const int pid = blockIdx.x - CONS_BLK;
        const int b0  = (pid & 127) << 4;    // b-tile (fastest -> chunk 0 first)
        const int cnk = pid >> 7;            // 16-t tile index 0..31
        const int t0  = cnk << 4;

        if (tx < 128) ws4[tx] = ((const float4*)W_ih0)[tx];
        if (tx < 16)  ws4[128 + tx] = ((const float4*)W_ih0)[128 + tx];
        if (tx < 9)   bs[tx] = b_ih0[tx];

        // Stage 16 b-rows x 16 t x 16 f4 (4 KB contiguous per b-row).
        const float4* xg = (const float4*)x;
#pragma unroll
        for (int c = 0; c < 32; c++) {
            int f   = (c << 7) + tx;         // 0..4095
            int bl  = f >> 8;                // 256 f4 per b-row
            int off = f & 255;
            xs[bl * XS_STRIDE + off] = xg[((size_t)(b0 + bl) * TT + t0) * 16 + off];
        }
        __syncthreads();

        const int b_loc = tx & 15;
        const int tp    = tx >> 4;           // 0..7 -> t-cells 2tp, 2tp+1
        const int tl0   = tp * 2;

        float acc0[9], acc1[9];
#pragma unroll
        for (int g = 0; g < 9; g++) { acc0[g] = bs[g]; acc1[g] = bs[g]; }

#pragma unroll
        for (int i = 0; i < 16; i++) {
            float4 xv0 = xs[b_loc * XS_STRIDE + tl0 * 16 + i];
            float4 xv1 = xs[b_loc * XS_STRIDE + (tl0 + 1) * 16 + i];
#pragma unroll
            for (int g = 0; g < 9; g++) {
                float4 wv = ws4[g * 16 + i];
                acc0[g] = fmaf(xv0.w, wv.w, fmaf(xv0.z, wv.z,
                          fmaf(xv0.y, wv.y, fmaf(xv0.x, wv.x, acc0[g]))));
                acc1[g] = fmaf(xv1.w, wv.w, fmaf(xv1.z, wv.z,
                          fmaf(xv1.y, wv.y, fmaf(xv1.x, wv.x, acc1[g]))));
            }
        }

#pragma unroll
        for (int g = 0; g < 3; g++) {
            os[(tl0 * 3 + g) * 16 + b_loc] =
                make_float4(acc0[g], acc0[3 + g], acc0[6 + g], 0.f);
            os[((tl0 + 1) * 3 + g) * 16 + b_loc] =
                make_float4(acc1[g], acc1[3 + g], acc1[6 + g], 0.f);
        }
        __syncthreads();

        // 768 float4 out, 128 threads x 6 rounds, lanes consecutive in b.
#pragma unroll
        for (int r = 0; r < 6; r++) {
            int f    = r * 128 + tx;
            int pair = f >> 4;               // tt*3 + g  (0..47)
            int bl   = f & 15;
            int tt   = pair / 3, gg = pair % 3;
            g_xw4[((size_t)(t0 + tt) * 3 + gg) * BB + b0 + bl] = os[pair * 16 + bl];
        }

        __threadfence();
        __syncthreads();
        if (tx == 0) {                       // tile spans 8t-chunks 2cnk, 2cnk+1
            atomicAdd(&g_flags[2 * cnk], 1);
            atomicAdd(&g_flags[2 * cnk + 1], 1);
        }
        return;
    }

    // =============== CONSUMER ===============
    const int lane = tx & 31;
    const int gw   = blockIdx.x * 4 + (tx >> 5);   // global warp 0..255
    const int j    = lane & 3;
    const int base = lane & ~3;
    const bool dum = (j == 3);
    const int g    = dum ? 0 : j;
    const int e    = gw * 8 + (lane >> 2);

    float wh0[3][3], wi1[3][3], wh1[3][3], bh0[3], bi1[3], bh1[3];
#pragma unroll
    for (int q = 0; q < 3; q++) {
        int row = q * 3 + g;
        bh0[q] = __ldg(b_hh0 + row);
        bi1[q] = __ldg(b_ih1 + row);
        bh1[q] = __ldg(b_hh1 + row);
#pragma unroll
        for (int k = 0; k < 3; k++) {
            wh0[q][k] = __ldg(W_hh0 + row * 3 + k);
            wi1[q][k] = __ldg(W_ih1 + row * 3 + k);
            wh1[q][k] = __ldg(W_hh1 + row * 3 + k);
        }
    }

    float hA = 0.f;   // h0[g]
    float hB = 0.f;   // h1[g]

    const size_t  xstr = dum ? 0 : (size_t)(3 * BB);
    const float4* xb   = g_xw4 + (dum ? PAD_OFF : ((size_t)g * BB + e));

    while (acq_load(&g_flags[0]) < 128) __nanosleep(64);

    float4 buf[8];
#pragma unroll
    for (int s = 0; s < 8; s++) buf[s] = xb[(size_t)s * xstr];

    const unsigned FULL = 0xffffffffu;

    int fv = acq_load(&g_flags[1]);

    for (int t8 = 0; t8 < 64; t8++) {
        if (t8 < 63) {
            if (fv < 128) {
                while (acq_load(&g_flags[t8 + 1]) < 128) __nanosleep(64);
            }
            int nxt = (t8 + 2 < 64) ? t8 + 2 : 63;
            fv = acq_load(&g_flags[nxt]);
        }

#pragma unroll
        for (int i = 0; i < 8; i++) {
            const int t = t8 * 8 + i;
            float4 b4 = buf[i];
            buf[i] = xb[(size_t)(t + 8) * xstr];

            float a0 = __shfl_sync(FULL, hA, base + 0);
            float a1 = __shfl_sync(FULL, hA, base + 1);
            float a2 = __shfl_sync(FULL, hA, base + 2);
            float c0 = __shfl_sync(FULL, hB, base + 0);
            float c1 = __shfl_sync(FULL, hB, base + 1);
            float c2 = __shfl_sync(FULL, hB, base + 2);

            float g0r = fmaf(wh0[0][2], a2, fmaf(wh0[0][1], a1, fmaf(wh0[0][0], a0, bh0[0])));
            float g0z = fmaf(wh0[1][2], a2, fmaf(wh0[1][1], a1, fmaf(wh0[1][0], a0, bh0[1])));
            float g0n = fmaf(wh0[2][2], a2, fmaf(wh0[2][1], a1, fmaf(wh0[2][0], a0, bh0[2])));
            float r0  = sigm(b4.x + g0r);
            float z0  = sigm(b4.y + g0z);
            float n0  = tanh_fast(fmaf(r0, g0n, b4.z));
            float hAn = fmaf(z0, hA - n0, n0);

            float i1r = fmaf(wi1[0][2], a2, fmaf(wi1[0][1], a1, fmaf(wi1[0][0], a0, bi1[0])));
            float i1z = fmaf(wi1[1][2], a2, fmaf(wi1[1][1], a1, fmaf(wi1[1][0], a0, bi1[1])));
            float i1n = fmaf(wi1[2][2], a2, fmaf(wi1[2][1], a1, fmaf(wi1[2][0], a0, bi1[2])));
            float g1r = fmaf(wh1[0][2], c2, fmaf(wh1[0][1], c1, fmaf(wh1[0][0], c0, bh1[0])));
            float g1z = fmaf(wh1[1][2], c2, fmaf(wh1[1][1], c1, fmaf(wh1[1][0], c0, bh1[1])));
            float g1n = fmaf(wh1[2][2], c2, fmaf(wh1[2][1], c1, fmaf(wh1[2][0], c0, bh1[2])));
            float r1  = sigm(i1r + g1r);
            float z1  = sigm(i1z + g1z);
            float n1  = tanh_fast(fmaf(r1, g1n, i1n));
            float hBn = fmaf(z1, hB - n1, n1);

            hA = hAn;
            hB = (t == 0) ? 0.f : hBn;
        }
    }

    // Epilogue: layer-1 consumes h0^{T-1}.
    {
        float a0 = __shfl_sync(FULL, hA, base + 0);
        float a1 = __shfl_sync(FULL, hA, base + 1);
        float a2 = __shfl_sync(FULL, hA, base + 2);
        float c0 = __shfl_sync(FULL, hB, base + 0);
        float c1 = __shfl_sync(FULL, hB, base + 1);
        float c2 = __shfl_sync(FULL, hB, base + 2);

        float i1r = fmaf(wi1[0][2], a2, fmaf(wi1[0][1], a1, fmaf(wi1[0][0], a0, bi1[0])));
        float i1z = fmaf(wi1[1][2], a2, fmaf(wi1[1][1], a1, fmaf(wi1[1][0], a0, bi1[1])));
        float i1n = fmaf(wi1[2][2], a2, fmaf(wi1[2][1], a1, fmaf(wi1[2][0], a0, bi1[2])));
        float g1r = fmaf(wh1[0][2], c2, fmaf(wh1[0][1], c1, fmaf(wh1[0][0], c0, bh1[0])));
        float g1z = fmaf(wh1[1][2], c2, fmaf(wh1[1][1], c1, fmaf(wh1[1][0], c0, bh1[1])));
        float g1n = fmaf(wh1[2][2], c2, fmaf(wh1[2][1], c1, fmaf(wh1[2][0], c0, bh1[2])));
        float r1  = sigm(i1r + g1r);
        float z1  = sigm(i1z + g1z);
        float n1  = tanh_fast(fmaf(r1, g1n, i1n));
        hB = fmaf(z1, hB - n1, n1);
    }

    if (j < 3)
        out[e * 3 + j] = hB;
}

extern "C" void kernel_launch(void* const* d_in, const int* in_sizes, int n_in,
                              void* d_out, int out_size)
{
    const float* x     = (const float*)d_in[0];
    const float* W_ih0 = (const float*)d_in[1];
    const float* W_hh0 = (const float*)d_in[2];
    const float* b_ih0 = (const float*)d_in[3];
    const float* b_hh0 = (const float*)d_in[4];
    const float* W_ih1 = (const float*)d_in[5];
    const float* W_hh1 = (const float*)d_in[6];
    const float* b_ih1 = (const float*)d_in[7];
    const float* b_hh1 = (const float*)d_in[8];
    float* out = (float*)d_out;

    cudaFuncSetAttribute(fused, cudaFuncAttributeMaxDynamicSharedMemorySize, XS_BYTES);

    reset_flags<<<1, 64>>>();
    fused<<<CONS_BLK + PROD_BLK, 128, XS_BYTES>>>(
        x, W_ih0, b_ih0, W_hh0, b_hh0, W_ih1, b_ih1, W_hh1, b_hh1, out);
}